// round 7
// baseline (speedup 1.0000x reference)
#include <cuda_runtime.h>
#include <math.h>

// ---------------------------------------------------------------------------
// RobiiNetV2: 10 iterations x 512 sequential block steps over complex data.
//   B=8 batches, W=64 block width, DIM=1024, N=32768 (y + conj(y)).
// Persistent single kernel, 128 CTAs, software grid barrier (ticket flags).
// R6: Phase A loads vectorized to float4 (H rows + smem x staging).
// ---------------------------------------------------------------------------

#define B_      8
#define W_      64
#define NB_     512
#define DIM_    1024
#define NH_     16384
#define NITER_  10
#define GRID_   128
#define TPB_    256
#define THRESH_ 1e-3f
#define INV_WD  (1.0f/65536.0f)   // 1/(W*DIM)

// ------------------------- global scratch (static) -------------------------
__device__ float g_x_re[B_*DIM_];
__device__ float g_x_im[B_*DIM_];
__device__ float g_r_re[B_*W_];
__device__ float g_r_im[B_*W_];
__device__ float g_a2 [B_*W_];
__device__ float g_tau[2][NB_*B_*W_];
__device__ float g_maxpart[GRID_];
__device__ unsigned g_barflags[GRID_];

// ------------------------------- shared mem --------------------------------
struct Smem {
  float wT_estep [W_*W_];   // transposed: [w][j]
  float wT_update[W_*W_];
  float wT_memory[W_*W_];
  float b_estep[W_], b_update[W_], b_memory[W_];
  float sx_re[DIM_], sx_im[DIM_];   // 16B-aligned within struct
  float sa2[B_*W_];
  float sr_re[W_], sr_im[W_], stau[W_], sht[W_];
  float sres_re[W_], sres_im[W_];
  float red[2*TPB_];
  float szr[8], szi[8];
};

// ----------------------- grid barrier (ticket-based) -----------------------
// Monotonic tickets: no flag reset between barriers. Flags zeroed by init
// kernel each launch. __threadfence() is gpu-scope -> orders writes AND (per
// sm_103a behavior) invalidates L1D so post-barrier normal loads see fresh
// data from other CTAs.
__device__ __forceinline__ void gridbar(unsigned ticket) {
  __syncthreads();
  __threadfence();
  if (threadIdx.x == 0) atomicExch(&g_barflags[blockIdx.x], ticket);
  if (threadIdx.x < GRID_) {
    volatile unsigned* f = g_barflags;
    while (f[threadIdx.x] < ticket) { }
  }
  __threadfence();
  __syncthreads();
}

// ------------------------------- init kernel -------------------------------
__global__ void __launch_bounds__(TPB_) robii_init() {
  int idx = blockIdx.x * blockDim.x + threadIdx.x;
  if (idx < NB_*B_*W_) g_tau[0][idx] = 1.0f;
  if (idx < B_*DIM_) { g_x_re[idx] = 0.0f; g_x_im[idx] = 0.0f; }
  if (idx < GRID_)   g_barflags[idx] = 0u;
}

// ------------------------------- main kernel -------------------------------
__global__ void __launch_bounds__(TPB_, 1) robii_main(
    const float* __restrict__ y_re,   const float* __restrict__ y_im,
    const float* __restrict__ H_re,   const float* __restrict__ H_im,
    const float* __restrict__ estep_w, const float* __restrict__ estep_b,
    const float* __restrict__ update_w, const float* __restrict__ update_b,
    const float* __restrict__ memory_w, const float* __restrict__ memory_b,
    float* __restrict__ out) {
  extern __shared__ unsigned char smem_raw[];
  Smem& s = *reinterpret_cast<Smem*>(smem_raw);

  const int c    = blockIdx.x;
  const int tid  = threadIdx.x;
  const int b    = c >> 4;          // batch handled by this CTA (16 CTAs per b)
  const int grp  = c & 15;          // w-group (phase A) / d-slice (phase C)
  const int warp = tid >> 5, lane = tid & 31;

  // Load weights (transposed for conflict-free GEMV) + biases, once.
  for (int idx = tid; idx < W_*W_; idx += TPB_) {
    int j = idx >> 6, w = idx & 63;
    s.wT_estep [w*W_ + j] = estep_w[idx];
    s.wT_update[w*W_ + j] = update_w[idx];
    s.wT_memory[w*W_ + j] = memory_w[idx];
  }
  if (tid < W_) {
    s.b_estep[tid]  = estep_b[tid];
    s.b_update[tid] = update_b[tid];
    s.b_memory[tid] = memory_b[tid];
  }
  __syncthreads();

  unsigned ticket = 0;

  for (int it = 0; it < NITER_; ++it) {
    const float* tau_in  = g_tau[it & 1];
    float*       tau_out = g_tau[(it & 1) ^ 1];

    for (int blk = 0; blk < NB_; ++blk) {
      // ================= Phase A: zk = x @ H^T, r = y - zk, a2 =============
      // Stage x[b] into smem: one float4 per thread per array (8 KB each).
      {
        const float4* gxr4 = reinterpret_cast<const float4*>(g_x_re + b*DIM_);
        const float4* gxi4 = reinterpret_cast<const float4*>(g_x_im + b*DIM_);
        reinterpret_cast<float4*>(s.sx_re)[tid] = gxr4[tid];
        reinterpret_cast<float4*>(s.sx_im)[tid] = gxi4[tid];
      }
      __syncthreads();
      {
        // 8 warps: warps (2j, 2j+1) split K for output w = grp*4 + j
        const int j = warp >> 1, half = warp & 1;
        const int w = grp*4 + j;
        const int row = blk*W_ + w;
        const float4* hr4 = reinterpret_cast<const float4*>(
                              H_re + (size_t)row*DIM_ + half*512);
        const float4* hi4 = reinterpret_cast<const float4*>(
                              H_im + (size_t)row*DIM_ + half*512);
        const float4* xr4 = reinterpret_cast<const float4*>(s.sx_re + half*512);
        const float4* xi4 = reinterpret_cast<const float4*>(s.sx_im + half*512);
        float zr = 0.f, zi = 0.f;
        #pragma unroll
        for (int k = 0; k < 4; ++k) {
          int d = lane + 32*k;                  // 128 float4 per warp-half
          float4 a4 = hr4[d], b4 = hi4[d];
          float4 u4 = xr4[d], v4 = xi4[d];
          zr += u4.x*a4.x - v4.x*b4.x;  zi += u4.x*b4.x + v4.x*a4.x;
          zr += u4.y*a4.y - v4.y*b4.y;  zi += u4.y*b4.y + v4.y*a4.y;
          zr += u4.z*a4.z - v4.z*b4.z;  zi += u4.z*b4.z + v4.z*a4.z;
          zr += u4.w*a4.w - v4.w*b4.w;  zi += u4.w*b4.w + v4.w*a4.w;
        }
        #pragma unroll
        for (int o = 16; o > 0; o >>= 1) {
          zr += __shfl_xor_sync(0xffffffffu, zr, o);
          zi += __shfl_xor_sync(0xffffffffu, zi, o);
        }
        if (lane == 0) { s.szr[warp] = zr; s.szi[warp] = zi; }
      }
      __syncthreads();
      if (tid < 4) {
        int w  = grp*4 + tid;
        float zr = s.szr[2*tid] + s.szr[2*tid+1];
        float zi = s.szi[2*tid] + s.szi[2*tid+1];
        int n = blk*W_ + w;
        float yr, yi;
        if (n < NH_) { yr = y_re[b*NH_ + n];        yi =  y_im[b*NH_ + n]; }
        else         { yr = y_re[b*NH_ + n - NH_];  yi = -y_im[b*NH_ + n - NH_]; }
        float rr = yr - zr, ri = yi - zi;
        g_r_re[b*W_ + w] = rr;
        g_r_im[b*W_ + w] = ri;
        g_a2 [b*W_ + w] = rr*rr + ri*ri;
      }
      gridbar(++ticket);

      // ====== Phase B (redundant per CTA): stats, tau, residual ============
      float v1 = g_a2[tid], v2 = g_a2[tid + TPB_];
      s.sa2[tid] = v1; s.sa2[tid + TPB_] = v2;
      if (tid < W_) {
        s.sr_re[tid] = g_r_re[b*W_ + tid];
        s.sr_im[tid] = g_r_im[b*W_ + tid];
        s.stau[tid]  = tau_in[(blk*B_ + b)*W_ + tid];
      }
      s.red[tid]        = v1 + v2;
      s.red[TPB_ + tid] = v1*v1 + v2*v2;
      __syncthreads();
      #pragma unroll
      for (int o = 128; o > 0; o >>= 1) {
        if (tid < o) {
          s.red[tid]        += s.red[tid + o];
          s.red[TPB_ + tid] += s.red[TPB_ + tid + o];
        }
        __syncthreads();
      }
      // per-batch mean of a2 (sigma2) via warp 0, broadcast through smem
      if (warp == 0) {
        float v = s.sa2[b*W_ + lane] + s.sa2[b*W_ + 32 + lane];
        #pragma unroll
        for (int o = 16; o > 0; o >>= 1) v += __shfl_xor_sync(0xffffffffu, v, o);
        if (lane == 0) s.szr[0] = v * (1.0f/64.0f);
      }
      __syncthreads();
      const float sigma2 = s.szr[0];
      const float sum = s.red[0], sumsq = s.red[TPB_];
      const float var = (sumsq - sum*sum*(1.0f/512.0f)) * (1.0f/511.0f);
      const float inv_std = rsqrtf(var);

      if (tid < W_) {
        float acc = s.b_estep[tid];
        #pragma unroll 8
        for (int w = 0; w < W_; ++w)
          acc += (s.sa2[b*W_ + w] * inv_std) * s.wT_estep[w*W_ + tid];
        s.sht[tid] = 1.0f / (1.0f + expf(-acc));
      }
      __syncthreads();
      if (tid < W_) {
        float acc = s.b_update[tid] + s.b_memory[tid];
        #pragma unroll 8
        for (int w = 0; w < W_; ++w)
          acc += s.sht[w]*s.wT_update[w*W_ + tid] + s.stau[w]*s.wT_memory[w*W_ + tid];
        float tn = fmaxf(acc, 0.0f);
        if (grp == 0) tau_out[(blk*B_ + b)*W_ + tid] = tn;   // single writer
        float sc = tn / sigma2;                               // MSTEP = 1
        s.sres_re[tid] = s.sr_re[tid]*sc;
        s.sres_im[tid] = s.sr_im[tid]*sc;
      }
      __syncthreads();

      // ====== Phase C: x[b, d-slice] += residual @ conj(H) / (W*DIM) =======
      {
        const int dd = grp*64 + (tid & 63);
        const int wq = tid >> 6;
        float ar = 0.f, ai = 0.f;
        #pragma unroll
        for (int k = 0; k < 16; ++k) {
          int w = wq*16 + k;
          size_t off = (size_t)(blk*W_ + w)*DIM_ + dd;
          float a = H_re[off], bb = H_im[off];
          float rr = s.sres_re[w], ri = s.sres_im[w];
          ar += rr*a + ri*bb;     // residual * conj(H)
          ai += ri*a - rr*bb;
        }
        s.red[tid] = ar; s.red[TPB_ + tid] = ai;
        __syncthreads();
        if (tid < 64) {
          float fr = s.red[tid] + s.red[tid+64] + s.red[tid+128] + s.red[tid+192];
          float fi = s.red[TPB_+tid] + s.red[TPB_+tid+64]
                   + s.red[TPB_+tid+128] + s.red[TPB_+tid+192];
          int gi = b*DIM_ + grp*64 + tid;   // this CTA exclusively owns slice
          g_x_re[gi] += fr * INV_WD;
          g_x_im[gi] += fi * INV_WD;
        }
      }
      gridbar(++ticket);
    } // blk

    // ================= soft threshold: x = sgn(x)*relu(|x| - t*max|x|) =====
    {
      float pm = 0.f;
      if (tid < 64) {
        int gi = c*64 + tid;   // == b*DIM + grp*64 + tid (CTA's own slice)
        float xr = g_x_re[gi], xi = g_x_im[gi];
        pm = sqrtf(xr*xr + xi*xi);
      }
      s.red[tid] = (tid < 64) ? pm : 0.f;
      __syncthreads();
      #pragma unroll
      for (int o = 128; o > 0; o >>= 1) {
        if (tid < o) s.red[tid] = fmaxf(s.red[tid], s.red[tid + o]);
        __syncthreads();
      }
      if (tid == 0) g_maxpart[c] = s.red[0];
      gridbar(++ticket);
      s.red[tid] = (tid < GRID_) ? g_maxpart[tid] : 0.f;
      __syncthreads();
      #pragma unroll
      for (int o = 128; o > 0; o >>= 1) {
        if (tid < o) s.red[tid] = fmaxf(s.red[tid], s.red[tid + o]);
        __syncthreads();
      }
      const float m = s.red[0];
      if (tid < 64) {
        int gi = c*64 + tid;
        float xr = g_x_re[gi], xi = g_x_im[gi];
        float ax = sqrtf(xr*xr + xi*xi);
        float t  = fmaxf(ax - THRESH_*m, 0.0f);
        float sc = (ax > 0.0f) ? (t/ax) : 0.0f;
        g_x_re[gi] = xr*sc;
        g_x_im[gi] = xi*sc;
      }
      gridbar(++ticket);
    }
  } // it

  // ============================ write outputs ==============================
  // out[0 .. 8191]           = real(x)  as [b][d]
  // out[8192 .. 8192+262143] = tau_out  as [b][blk][w]  (final tau in buf 0)
  if (tid < 64) {
    int gi = c*64 + tid;
    out[gi] = g_x_re[gi];
  }
  #pragma unroll
  for (int k = 0; k < 8; ++k) {
    int idx = c*2048 + tid + TPB_*k;          // 0 .. 262143
    int b2  = idx >> 15;
    int rem = idx & 32767;
    int ii  = rem >> 6;
    int w2  = rem & 63;
    out[B_*DIM_ + idx] = g_tau[0][(ii*B_ + b2)*W_ + w2];
  }
}

// ------------------------------ launch glue --------------------------------
extern "C" void kernel_launch(void* const* d_in, const int* in_sizes, int n_in,
                              void* d_out, int out_size) {
  const float* y_re     = (const float*)d_in[0];
  const float* y_im     = (const float*)d_in[1];
  const float* H_re     = (const float*)d_in[2];
  const float* H_im     = (const float*)d_in[3];
  const float* estep_w  = (const float*)d_in[4];
  const float* estep_b  = (const float*)d_in[5];
  const float* update_w = (const float*)d_in[6];
  const float* update_b = (const float*)d_in[7];
  const float* memory_w = (const float*)d_in[8];
  const float* memory_b = (const float*)d_in[9];
  float* out = (float*)d_out;

  cudaFuncSetAttribute(robii_main,
                       cudaFuncAttributeMaxDynamicSharedMemorySize,
                       (int)sizeof(Smem));

  robii_init<<<(NB_*B_*W_ + TPB_ - 1)/TPB_, TPB_>>>();
  robii_main<<<GRID_, TPB_, sizeof(Smem)>>>(
      y_re, y_im, H_re, H_im, estep_w, estep_b,
      update_w, update_b, memory_w, memory_b, out);
}

// round 9
// speedup vs baseline: 1.1403x; 1.1403x over previous
#include <cuda_runtime.h>
#include <math.h>

// ---------------------------------------------------------------------------
// RobiiNetV2 persistent kernel. R7:
//  - single-counter grid barrier (1 arrival + 1 poller per CTA)
//  - cp.async double-buffered prefetch of Phase-A H rows into smem
//  - Phase B: shuffle reductions + 4-way-split GEMVs over 256 threads
// ---------------------------------------------------------------------------

#define B_      8
#define W_      64
#define NB_     512
#define DIM_    1024
#define NH_     16384
#define NITER_  10
#define GRID_   128
#define TPB_    256
#define THRESH_ 1e-3f
#define INV_WD  (1.0f/65536.0f)   // 1/(W*DIM)

// ------------------------- global scratch (static) -------------------------
__device__ float g_x_re[B_*DIM_];
__device__ float g_x_im[B_*DIM_];
__device__ float g_r_re[B_*W_];
__device__ float g_r_im[B_*W_];
__device__ float g_a2 [B_*W_];
__device__ float g_tau[2][NB_*B_*W_];
__device__ float g_maxpart[GRID_];
__device__ unsigned g_barcount;

// ------------------------------- shared mem --------------------------------
struct __align__(16) Smem {
  float shH[2][2][4][DIM_];   // [buf][re/im][row j][d]  = 64 KB, 16B aligned
  float wT_estep [W_*W_];     // transposed: [w][j]
  float wT_update[W_*W_];
  float wT_memory[W_*W_];
  float b_estep[W_], b_update[W_], b_memory[W_];
  float sx_re[DIM_], sx_im[DIM_];
  float sa2[B_*W_];
  float sr_re[W_], sr_im[W_], stau[W_], sht[W_];
  float sres_re[W_], sres_im[W_];
  float red[2*TPB_];
  float szr[16], szi[16];
};

// ------------------------ cp.async helpers ---------------------------------
__device__ __forceinline__ void cp_async16(void* smem_dst, const void* gmem_src) {
  unsigned s = (unsigned)__cvta_generic_to_shared(smem_dst);
  asm volatile("cp.async.cg.shared.global [%0], [%1], 16;\n"
               :: "r"(s), "l"(gmem_src));
}
__device__ __forceinline__ void cp_async_commit() {
  asm volatile("cp.async.commit_group;\n");
}
__device__ __forceinline__ void cp_async_wait1() {
  asm volatile("cp.async.wait_group 1;\n");
}

// ----------------------- grid barrier (single counter) ---------------------
// Monotonic: barrier #t waits for count >= t*GRID_. One arrival + one poller
// per CTA; __syncthreads() CTA-level memory semantics publish all threads'
// prior writes to thread 0, whose gpu-scope fence (CCTL.IVALL) publishes to
// gpu scope and, post-wait, invalidates this SM's L1D for fresh reads.
__device__ __forceinline__ void gridbar(unsigned ticket) {
  __syncthreads();
  if (threadIdx.x == 0) {
    __threadfence();
    atomicAdd(&g_barcount, 1u);
    volatile unsigned* p = &g_barcount;
    const unsigned target = ticket * (unsigned)GRID_;
    while (*p < target) { }
    __threadfence();
  }
  __syncthreads();
}

// ------------------------------- init kernel -------------------------------
__global__ void __launch_bounds__(TPB_) robii_init() {
  int idx = blockIdx.x * blockDim.x + threadIdx.x;
  if (idx < NB_*B_*W_) g_tau[0][idx] = 1.0f;
  if (idx < B_*DIM_) { g_x_re[idx] = 0.0f; g_x_im[idx] = 0.0f; }
  if (idx == 0)      g_barcount = 0u;
}

// ------------------------------- main kernel -------------------------------
__global__ void __launch_bounds__(TPB_, 1) robii_main(
    const float* __restrict__ y_re,   const float* __restrict__ y_im,
    const float* __restrict__ H_re,   const float* __restrict__ H_im,
    const float* __restrict__ estep_w, const float* __restrict__ estep_b,
    const float* __restrict__ update_w, const float* __restrict__ update_b,
    const float* __restrict__ memory_w, const float* __restrict__ memory_b,
    float* __restrict__ out) {
  extern __shared__ unsigned char smem_raw[];
  Smem& s = *reinterpret_cast<Smem*>(smem_raw);

  const int c    = blockIdx.x;
  const int tid  = threadIdx.x;
  const int b    = c >> 4;          // batch handled by this CTA (16 CTAs per b)
  const int grp  = c & 15;          // w-group (phase A) / d-slice (phase C)
  const int warp = tid >> 5, lane = tid & 31;

  // Load weights (transposed for conflict-free GEMV) + biases, once.
  for (int idx = tid; idx < W_*W_; idx += TPB_) {
    int j = idx >> 6, w = idx & 63;
    s.wT_estep [w*W_ + j] = estep_w[idx];
    s.wT_update[w*W_ + j] = update_w[idx];
    s.wT_memory[w*W_ + j] = memory_w[idx];
  }
  if (tid < W_) {
    s.b_estep[tid]  = estep_b[tid];
    s.b_update[tid] = update_b[tid];
    s.b_memory[tid] = memory_b[tid];
  }

  // Prefetch issuer: 2048 16B chunks per buffer, 8 per thread.
  // chunk c: arr = c>>10, row = (c>>8)&3, off16 = c&255
  auto issue_prefetch = [&](int blkidx, int buf) {
    const int base_row = blkidx * W_ + grp * 4;
    #pragma unroll
    for (int k = 0; k < 8; ++k) {
      int ch  = tid + TPB_ * k;
      int arr = ch >> 10;
      int row = (ch >> 8) & 3;
      int off = ch & 255;
      const float* src = (arr ? H_im : H_re)
                         + (size_t)(base_row + row) * DIM_ + off * 4;
      cp_async16(&s.shH[buf][arr][row][off * 4], src);
    }
    cp_async_commit();
  };

  // Initial prefetch for blk=0 into buf 0.
  issue_prefetch(0, 0);
  __syncthreads();

  unsigned ticket = 0;

  for (int it = 0; it < NITER_; ++it) {
    const float* tau_in  = g_tau[it & 1];
    float*       tau_out = g_tau[(it & 1) ^ 1];

    for (int blk = 0; blk < NB_; ++blk) {
      const int buf = blk & 1;

      // ================= Phase A: zk = x @ H^T, r = y - zk, a2 =============
      // Stage x[b] into smem (one float4 per thread per array).
      {
        const float4* gxr4 = reinterpret_cast<const float4*>(g_x_re + b*DIM_);
        const float4* gxi4 = reinterpret_cast<const float4*>(g_x_im + b*DIM_);
        reinterpret_cast<float4*>(s.sx_re)[tid] = gxr4[tid];
        reinterpret_cast<float4*>(s.sx_im)[tid] = gxi4[tid];
      }
      // Kick off prefetch of the NEXT block's H rows, then wait for current.
      issue_prefetch((blk + 1) & (NB_ - 1), buf ^ 1);
      cp_async_wait1();                 // waits the group issued last step
      __syncthreads();
      {
        // 8 warps: warps (2j, 2j+1) split K for output w = grp*4 + j
        const int j = warp >> 1, half = warp & 1;
        const float4* hr4 = reinterpret_cast<const float4*>(
                              &s.shH[buf][0][j][half*512]);
        const float4* hi4 = reinterpret_cast<const float4*>(
                              &s.shH[buf][1][j][half*512]);
        const float4* xr4 = reinterpret_cast<const float4*>(s.sx_re + half*512);
        const float4* xi4 = reinterpret_cast<const float4*>(s.sx_im + half*512);
        float zr = 0.f, zi = 0.f;
        #pragma unroll
        for (int k = 0; k < 4; ++k) {
          int d = lane + 32*k;
          float4 a4 = hr4[d], b4 = hi4[d];
          float4 u4 = xr4[d], v4 = xi4[d];
          zr += u4.x*a4.x - v4.x*b4.x;  zi += u4.x*b4.x + v4.x*a4.x;
          zr += u4.y*a4.y - v4.y*b4.y;  zi += u4.y*b4.y + v4.y*a4.y;
          zr += u4.z*a4.z - v4.z*b4.z;  zi += u4.z*b4.z + v4.z*a4.z;
          zr += u4.w*a4.w - v4.w*b4.w;  zi += u4.w*b4.w + v4.w*a4.w;
        }
        #pragma unroll
        for (int o = 16; o > 0; o >>= 1) {
          zr += __shfl_xor_sync(0xffffffffu, zr, o);
          zi += __shfl_xor_sync(0xffffffffu, zi, o);
        }
        if (lane == 0) { s.szr[warp] = zr; s.szi[warp] = zi; }
      }
      __syncthreads();
      if (tid < 4) {
        int w  = grp*4 + tid;
        float zr = s.szr[2*tid] + s.szr[2*tid+1];
        float zi = s.szi[2*tid] + s.szi[2*tid+1];
        int n = blk*W_ + w;
        float yr, yi;
        if (n < NH_) { yr = y_re[b*NH_ + n];        yi =  y_im[b*NH_ + n]; }
        else         { yr = y_re[b*NH_ + n - NH_];  yi = -y_im[b*NH_ + n - NH_]; }
        float rr = yr - zr, ri = yi - zi;
        g_r_re[b*W_ + w] = rr;
        g_r_im[b*W_ + w] = ri;
        g_a2 [b*W_ + w] = rr*rr + ri*ri;
      }
      gridbar(++ticket);

      // ====== Phase B (redundant per CTA): stats, tau, residual ============
      float v1 = g_a2[tid], v2 = g_a2[tid + TPB_];
      s.sa2[tid] = v1; s.sa2[tid + TPB_] = v2;
      if (tid < W_) {
        s.sr_re[tid] = g_r_re[b*W_ + tid];
        s.sr_im[tid] = g_r_im[b*W_ + tid];
        s.stau[tid]  = tau_in[(blk*B_ + b)*W_ + tid];
      }
      // global sum & sumsq over 512 values: warp shuffles + 8 partials
      {
        float sv = v1 + v2, sq = v1*v1 + v2*v2;
        #pragma unroll
        for (int o = 16; o > 0; o >>= 1) {
          sv += __shfl_xor_sync(0xffffffffu, sv, o);
          sq += __shfl_xor_sync(0xffffffffu, sq, o);
        }
        if (lane == 0) { s.szr[warp] = sv; s.szr[8 + warp] = sq; }
      }
      __syncthreads();
      if (warp == 0) {
        // per-batch sigma2 (mean of this b's 64 a2 values)
        float vb = s.sa2[b*W_ + lane] + s.sa2[b*W_ + 32 + lane];
        #pragma unroll
        for (int o = 16; o > 0; o >>= 1) vb += __shfl_xor_sync(0xffffffffu, vb, o);
        // global sums over the 8 warp partials
        float ssum = (lane < 8) ? s.szr[lane]     : 0.f;
        float ssq  = (lane < 8) ? s.szr[8 + lane] : 0.f;
        #pragma unroll
        for (int o = 4; o > 0; o >>= 1) {
          ssum += __shfl_xor_sync(0xffffffffu, ssum, o);
          ssq  += __shfl_xor_sync(0xffffffffu, ssq,  o);
        }
        if (lane == 0) {
          s.szi[0] = vb * (1.0f/64.0f);   // sigma2
          s.szi[1] = ssum;
          s.szi[2] = ssq;
        }
      }
      __syncthreads();
      const float sigma2 = s.szi[0];
      const float sum = s.szi[1], sumsq = s.szi[2];
      const float var = (sumsq - sum*sum*(1.0f/512.0f)) * (1.0f/511.0f);
      const float inv_std = rsqrtf(var);

      // GEMV 1 (estep): 256 threads, 4 partials per output j
      const int j = tid & 63, q = tid >> 6;
      {
        float acc = 0.f;
        #pragma unroll
        for (int k = 0; k < 16; ++k) {
          int w = q*16 + k;
          acc += s.sa2[b*W_ + w] * s.wT_estep[w*W_ + j];
        }
        s.red[tid] = acc * inv_std;
      }
      __syncthreads();
      if (tid < W_) {
        float a = s.red[tid] + s.red[tid+64] + s.red[tid+128] + s.red[tid+192]
                + s.b_estep[tid];
        s.sht[tid] = 1.0f / (1.0f + expf(-a));
      }
      __syncthreads();
      // GEMV 2 (update + memory)
      {
        float acc = 0.f;
        #pragma unroll
        for (int k = 0; k < 16; ++k) {
          int w = q*16 + k;
          acc += s.sht[w]  * s.wT_update[w*W_ + j]
               + s.stau[w] * s.wT_memory[w*W_ + j];
        }
        s.red[tid] = acc;
      }
      __syncthreads();
      if (tid < W_) {
        float a = s.red[tid] + s.red[tid+64] + s.red[tid+128] + s.red[tid+192]
                + s.b_update[tid] + s.b_memory[tid];
        float tn = fmaxf(a, 0.0f);
        if (grp == 0) tau_out[(blk*B_ + b)*W_ + tid] = tn;   // single writer
        float sc = tn / sigma2;                               // MSTEP = 1
        s.sres_re[tid] = s.sr_re[tid]*sc;
        s.sres_im[tid] = s.sr_im[tid]*sc;
      }
      __syncthreads();

      // ====== Phase C: x[b, d-slice] += residual @ conj(H) / (W*DIM) =======
      {
        const int dd = grp*64 + (tid & 63);
        const int wq = tid >> 6;
        float ar = 0.f, ai = 0.f;
        #pragma unroll
        for (int k = 0; k < 16; ++k) {
          int w = wq*16 + k;
          size_t off = (size_t)(blk*W_ + w)*DIM_ + dd;
          float a = H_re[off], bb = H_im[off];     // L2 hits (cp.async.cg fill)
          float rr = s.sres_re[w], ri = s.sres_im[w];
          ar += rr*a + ri*bb;     // residual * conj(H)
          ai += ri*a - rr*bb;
        }
        s.red[tid] = ar; s.red[TPB_ + tid] = ai;
        __syncthreads();
        if (tid < 64) {
          float fr = s.red[tid] + s.red[tid+64] + s.red[tid+128] + s.red[tid+192];
          float fi = s.red[TPB_+tid] + s.red[TPB_+tid+64]
                   + s.red[TPB_+tid+128] + s.red[TPB_+tid+192];
          int gi = b*DIM_ + grp*64 + tid;   // this CTA exclusively owns slice
          g_x_re[gi] += fr * INV_WD;
          g_x_im[gi] += fi * INV_WD;
        }
      }
      gridbar(++ticket);
    } // blk

    // ================= soft threshold: x = sgn(x)*relu(|x| - t*max|x|) =====
    {
      float pm = 0.f;
      if (tid < 64) {
        int gi = c*64 + tid;   // CTA's own slice
        float xr = g_x_re[gi], xi = g_x_im[gi];
        pm = sqrtf(xr*xr + xi*xi);
      }
      s.red[tid] = (tid < 64) ? pm : 0.f;
      __syncthreads();
      #pragma unroll
      for (int o = 128; o > 0; o >>= 1) {
        if (tid < o) s.red[tid] = fmaxf(s.red[tid], s.red[tid + o]);
        __syncthreads();
      }
      if (tid == 0) g_maxpart[c] = s.red[0];
      gridbar(++ticket);
      s.red[tid] = (tid < GRID_) ? g_maxpart[tid] : 0.f;
      __syncthreads();
      #pragma unroll
      for (int o = 128; o > 0; o >>= 1) {
        if (tid < o) s.red[tid] = fmaxf(s.red[tid], s.red[tid + o]);
        __syncthreads();
      }
      const float m = s.red[0];
      if (tid < 64) {
        int gi = c*64 + tid;
        float xr = g_x_re[gi], xi = g_x_im[gi];
        float ax = sqrtf(xr*xr + xi*xi);
        float t  = fmaxf(ax - THRESH_*m, 0.0f);
        float sc = (ax > 0.0f) ? (t/ax) : 0.0f;
        g_x_re[gi] = xr*sc;
        g_x_im[gi] = xi*sc;
      }
      gridbar(++ticket);
    }
  } // it

  // ============================ write outputs ==============================
  // out[0 .. 8191]           = real(x)  as [b][d]
  // out[8192 .. 8192+262143] = tau_out  as [b][blk][w]  (final tau in buf 0)
  if (tid < 64) {
    int gi = c*64 + tid;
    out[gi] = g_x_re[gi];
  }
  #pragma unroll
  for (int k = 0; k < 8; ++k) {
    int idx = c*2048 + tid + TPB_*k;          // 0 .. 262143
    int b2  = idx >> 15;
    int rem = idx & 32767;
    int ii  = rem >> 6;
    int w2  = rem & 63;
    out[B_*DIM_ + idx] = g_tau[0][(ii*B_ + b2)*W_ + w2];
  }
}

// ------------------------------ launch glue --------------------------------
extern "C" void kernel_launch(void* const* d_in, const int* in_sizes, int n_in,
                              void* d_out, int out_size) {
  const float* y_re     = (const float*)d_in[0];
  const float* y_im     = (const float*)d_in[1];
  const float* H_re     = (const float*)d_in[2];
  const float* H_im     = (const float*)d_in[3];
  const float* estep_w  = (const float*)d_in[4];
  const float* estep_b  = (const float*)d_in[5];
  const float* update_w = (const float*)d_in[6];
  const float* update_b = (const float*)d_in[7];
  const float* memory_w = (const float*)d_in[8];
  const float* memory_b = (const float*)d_in[9];
  float* out = (float*)d_out;

  cudaFuncSetAttribute(robii_main,
                       cudaFuncAttributeMaxDynamicSharedMemorySize,
                       (int)sizeof(Smem));

  robii_init<<<(NB_*B_*W_ + TPB_ - 1)/TPB_, TPB_>>>();
  robii_main<<<GRID_, TPB_, sizeof(Smem)>>>(
      y_re, y_im, H_re, H_im, estep_w, estep_b,
      update_w, update_b, memory_w, memory_b, out);
}